// round 17
// baseline (speedup 1.0000x reference)
#include <cuda_runtime.h>
#include <math_constants.h>

#define N_ROWS 1000000
#define M_SEG  50000
#define DIM    128
#define SCAN_B 1024
#define NB ((M_SEG + SCAN_B - 1) / SCAN_B)   // 49

#define GM_BM 128
#define GM_BK 8
#define GEMM_TILES ((M_SEG + GM_BM - 1) / GM_BM)   // 391
#define GEMM_HALF  196                              // tiles in fused A
#define HIST_BLKS  ((N_ROWS / 4 + 255) / 256)       // 977

// -------- device scratch (no runtime allocation allowed) --------
__device__ float4 g_keys_proj[M_SEG * 32];   // [M,128] as float4, 25.6 MB
__device__ float  g_probs[N_ROWS];           // per-row raw dot, 4 MB
__device__ float  g_inv[M_SEG];              // per-seg 1/sum(exp)
__device__ int    g_count[M_SEG];
__device__ int    g_offsets[M_SEG + 1];
__device__ int    g_cursor[M_SEG];
__device__ int    g_perm[N_ROWS];            // 4 MB
__device__ int    g_blocksum[NB];
__device__ int    g_blockpre[NB + 1];

// ------------------------------------------------------------------
__global__ void zero_count_kernel() {
    int i = blockIdx.x * blockDim.x + threadIdx.x;
    if (i < M_SEG) g_count[i] = 0;
}

// ------------------------------------------------------------------
// GEMM tile body: keys_proj[rows of tile] = A @ W^T + b. float4 loads.
__device__ __forceinline__ void gemm_tile_body(int tile,
                                               const float* __restrict__ A,
                                               const float* __restrict__ W,
                                               const float* __restrict__ b) {
    __shared__ float sA[GM_BK][GM_BM];
    __shared__ float sB[GM_BK][DIM];
    const int block_row = tile * GM_BM;
    const int tid = threadIdx.x;          // 256
    const int tx = tid % 16;
    const int ty = tid / 16;

    float acc[8][8];
#pragma unroll
    for (int i = 0; i < 8; i++)
#pragma unroll
        for (int j = 0; j < 8; j++) acc[i][j] = 0.f;

    // float4 tile loaders: 256 threads x 1 float4 = 1024 floats per tile
    const int lm = tid >> 1;              // row/col 0..127
    const int lk4 = (tid & 1) * 4;        // k sub-offset 0 or 4

    for (int k0 = 0; k0 < DIM; k0 += GM_BK) {
        int gm = block_row + lm;
        float4 av = (gm < M_SEG)
            ? *(const float4*)(A + (size_t)gm * DIM + k0 + lk4)
            : make_float4(0.f, 0.f, 0.f, 0.f);
        sA[lk4 + 0][lm] = av.x; sA[lk4 + 1][lm] = av.y;
        sA[lk4 + 2][lm] = av.z; sA[lk4 + 3][lm] = av.w;
        float4 wv = *(const float4*)(W + (size_t)lm * DIM + k0 + lk4);
        sB[lk4 + 0][lm] = wv.x; sB[lk4 + 1][lm] = wv.y;
        sB[lk4 + 2][lm] = wv.z; sB[lk4 + 3][lm] = wv.w;
        __syncthreads();
#pragma unroll
        for (int k = 0; k < GM_BK; ++k) {
            float ar[8], br[8];
#pragma unroll
            for (int j = 0; j < 8; j++) ar[j] = sA[k][ty * 8 + j];
#pragma unroll
            for (int j = 0; j < 8; j++) br[j] = sB[k][tx * 8 + j];
#pragma unroll
            for (int i = 0; i < 8; i++)
#pragma unroll
                for (int j = 0; j < 8; j++) acc[i][j] += ar[i] * br[j];
        }
        __syncthreads();
    }
    float4* kp4 = (float4*)g_keys_proj;
    const int c0 = tx * 8;
#pragma unroll
    for (int i = 0; i < 8; i++) {
        int gm = block_row + ty * 8 + i;
        if (gm < M_SEG) {
            float4 lo = make_float4(acc[i][0] + b[c0 + 0], acc[i][1] + b[c0 + 1],
                                    acc[i][2] + b[c0 + 2], acc[i][3] + b[c0 + 3]);
            float4 hi = make_float4(acc[i][4] + b[c0 + 4], acc[i][5] + b[c0 + 5],
                                    acc[i][6] + b[c0 + 6], acc[i][7] + b[c0 + 7]);
            kp4[gm * 32 + tx * 2]     = lo;
            kp4[gm * 32 + tx * 2 + 1] = hi;
        }
    }
}

// ------------------------------------------------------------------
// Fused A: first GEMM_HALF blocks do GEMM tiles, rest do histogram.
__global__ void fusedA_kernel(const float* __restrict__ A,
                              const float* __restrict__ W,
                              const float* __restrict__ b,
                              const int4* __restrict__ idx4) {
    if (blockIdx.x < GEMM_HALF) {
        gemm_tile_body(blockIdx.x, A, W, b);
    } else {
        int i = (blockIdx.x - GEMM_HALF) * blockDim.x + threadIdx.x;
        if (i < N_ROWS / 4) {
            int4 v = idx4[i];
            atomicAdd(&g_count[v.x], 1);
            atomicAdd(&g_count[v.y], 1);
            atomicAdd(&g_count[v.z], 1);
            atomicAdd(&g_count[v.w], 1);
        }
    }
}

// ------------------------------------------------------------------
// Fused B: first (GEMM_TILES-GEMM_HALF) blocks do remaining GEMM tiles,
// rest do the CSR scatter.
__global__ void fusedB_kernel(const float* __restrict__ A,
                              const float* __restrict__ W,
                              const float* __restrict__ b,
                              const int4* __restrict__ idx4) {
    const int ngemm = GEMM_TILES - GEMM_HALF;
    if (blockIdx.x < ngemm) {
        gemm_tile_body(GEMM_HALF + blockIdx.x, A, W, b);
    } else {
        int i = (blockIdx.x - ngemm) * blockDim.x + threadIdx.x;
        if (i < N_ROWS / 4) {
            int4 v = idx4[i];
            int r = i * 4;
            g_perm[atomicAdd(&g_cursor[v.x], 1)] = r;
            g_perm[atomicAdd(&g_cursor[v.y], 1)] = r + 1;
            g_perm[atomicAdd(&g_cursor[v.z], 1)] = r + 2;
            g_perm[atomicAdd(&g_cursor[v.w], 1)] = r + 3;
        }
    }
}

// ------------------------------------------------------------------
// 3a) per-block intra scan
__global__ void scan_phaseA() {
    __shared__ int warp_sums[32];
    const int tid = threadIdx.x, lane = tid & 31, wid = tid >> 5;
    const int i = blockIdx.x * SCAN_B + tid;
    int v = (i < M_SEG) ? g_count[i] : 0;
    int x = v;
#pragma unroll
    for (int o = 1; o < 32; o <<= 1) {
        int t = __shfl_up_sync(0xffffffffu, x, o);
        if (lane >= o) x += t;
    }
    if (lane == 31) warp_sums[wid] = x;
    __syncthreads();
    if (wid == 0) {
        int ws = warp_sums[lane];
#pragma unroll
        for (int o = 1; o < 32; o <<= 1) {
            int t = __shfl_up_sync(0xffffffffu, ws, o);
            if (lane >= o) ws += t;
        }
        warp_sums[lane] = ws;
    }
    __syncthreads();
    int wp = (wid == 0) ? 0 : warp_sums[wid - 1];
    if (i < M_SEG) g_offsets[i] = wp + x - v;
    if (tid == SCAN_B - 1) g_blocksum[blockIdx.x] = wp + x;
}

// 3b) scan block sums
__global__ void scan_phaseB() {
    __shared__ int warp_sums[2];
    const int tid = threadIdx.x, lane = tid & 31, wid = tid >> 5;
    int v = (tid < NB) ? g_blocksum[tid] : 0;
    int x = v;
#pragma unroll
    for (int o = 1; o < 32; o <<= 1) {
        int t = __shfl_up_sync(0xffffffffu, x, o);
        if (lane >= o) x += t;
    }
    if (lane == 31) warp_sums[wid] = x;
    __syncthreads();
    int wp = (wid == 1) ? warp_sums[0] : 0;
    if (tid < NB) g_blockpre[tid] = wp + x - v;
    if (tid == NB - 1) g_blockpre[NB] = wp + x;
}

// 3c) apply block prefix
__global__ void scan_phaseC() {
    const int i = blockIdx.x * SCAN_B + threadIdx.x;
    if (i < M_SEG) {
        int e = g_offsets[i] + g_blockpre[blockIdx.x];
        g_offsets[i] = e;
        g_cursor[i]  = e;
    }
    if (i == 0) g_offsets[M_SEG] = g_blockpre[NB];
}

// ------------------------------------------------------------------
// Segment kernel: single-pass no-max softmax, 4-lane groups, 8 rows/tile,
// next-tile perm prefetch, key row in shared.
__global__ void __launch_bounds__(128)
segment_kernel(const float4* __restrict__ SV,
               float4* __restrict__ out_applied) {
    __shared__ float4 skey[4][32];
    const int wib = threadIdx.x >> 5;
    const int seg = blockIdx.x * 4 + wib;
    const int lane = threadIdx.x & 31;
    if (seg >= M_SEG) return;
    const int g = lane >> 2;          // row-of-tile 0..7
    const int j = lane & 3;           // dim-slice 0..3
    const int start = g_offsets[seg];
    const int end   = g_offsets[seg + 1];

    skey[wib][lane] = g_keys_proj[(size_t)seg * 32 + lane];
    __syncwarp();

    float esum = 0.f;
    float4 acc[8];
#pragma unroll
    for (int i = 0; i < 8; i++) acc[i] = make_float4(0.f, 0.f, 0.f, 0.f);

    int rowcur = (start + g < end) ? g_perm[start + g] : 0;

    for (int base = start; base < end; base += 8) {
        const bool valid = (base + g < end);
        const int row = rowcur;
        // prefetch next tile's perm early (off the critical path)
        const int rn = base + 8 + g;
        const int rownext = (rn < end) ? g_perm[rn] : 0;

        float4 v[8];
#pragma unroll
        for (int i = 0; i < 8; i++)
            v[i] = valid ? __ldcs(&SV[(size_t)row * 32 + j + 4 * i])
                         : make_float4(0.f, 0.f, 0.f, 0.f);
        float d = 0.f;
#pragma unroll
        for (int i = 0; i < 8; i++) {
            float4 kv = skey[wib][j + 4 * i];
            d += v[i].x * kv.x + v[i].y * kv.y + v[i].z * kv.z + v[i].w * kv.w;
        }
        d += __shfl_xor_sync(0xffffffffu, d, 1);
        d += __shfl_xor_sync(0xffffffffu, d, 2);
        if (valid && j == 0) g_probs[row] = d;

        const float e = valid ? __expf(d) : 0.f;     // dots bounded ~|70| << 88
        esum += e;
#pragma unroll
        for (int i = 0; i < 8; i++) {
            acc[i].x += e * v[i].x;
            acc[i].y += e * v[i].y;
            acc[i].z += e * v[i].z;
            acc[i].w += e * v[i].w;
        }
        rowcur = rownext;
    }

    esum += __shfl_xor_sync(0xffffffffu, esum, 4);
    esum += __shfl_xor_sync(0xffffffffu, esum, 8);
    esum += __shfl_xor_sync(0xffffffffu, esum, 16);
    const float inv = (end > start) ? 1.f / esum : 0.f;
    if (lane == 0) g_inv[seg] = inv;

#pragma unroll
    for (int o = 4; o < 32; o <<= 1) {
#pragma unroll
        for (int i = 0; i < 8; i++) {
            acc[i].x += __shfl_xor_sync(0xffffffffu, acc[i].x, o);
            acc[i].y += __shfl_xor_sync(0xffffffffu, acc[i].y, o);
            acc[i].z += __shfl_xor_sync(0xffffffffu, acc[i].z, o);
            acc[i].w += __shfl_xor_sync(0xffffffffu, acc[i].w, o);
        }
    }
    float4 outv = acc[0];
#pragma unroll
    for (int i = 1; i < 8; i++) if (g == i) outv = acc[i];
    outv.x *= inv; outv.y *= inv; outv.z *= inv; outv.w *= inv;
    out_applied[(size_t)seg * 32 + lane] = outv;
}

// ------------------------------------------------------------------
// finalize: scores[i] = exp(probs[i]) * inv[idx[i]]
__global__ void finalize_kernel(const int4* __restrict__ idx4,
                                float4* __restrict__ out_scores4) {
    int i = blockIdx.x * blockDim.x + threadIdx.x;
    if (i >= N_ROWS / 4) return;
    int4 s = idx4[i];
    float4 p = ((const float4*)g_probs)[i];
    float4 r;
    r.x = __expf(p.x) * g_inv[s.x];
    r.y = __expf(p.y) * g_inv[s.y];
    r.z = __expf(p.z) * g_inv[s.z];
    r.w = __expf(p.w) * g_inv[s.w];
    out_scores4[i] = r;
}

// ------------------------------------------------------------------
extern "C" void kernel_launch(void* const* d_in, const int* in_sizes, int n_in,
                              void* d_out, int out_size) {
    const float4* SV   = (const float4*)d_in[0];   // [N, 128]
    const int4*   idx4 = (const int4*)d_in[1];     // [N] int32
    const float*  keys = (const float*)d_in[2];    // [M, 128]
    const float*  W    = (const float*)d_in[3];    // [128, 128]
    const float*  b    = (const float*)d_in[4];    // [128]

    float*  out_scores  = (float*)d_out;                   // [N]
    float4* out_applied = (float4*)(out_scores + N_ROWS);  // [M, 128]

    zero_count_kernel<<<(M_SEG + 255) / 256, 256>>>();
    // GEMM first half overlapped with histogram
    fusedA_kernel<<<GEMM_HALF + HIST_BLKS, 256>>>(keys, W, b, idx4);
    scan_phaseA<<<NB, SCAN_B>>>();
    scan_phaseB<<<1, 64>>>();
    scan_phaseC<<<NB, SCAN_B>>>();
    // GEMM second half overlapped with CSR scatter
    fusedB_kernel<<<(GEMM_TILES - GEMM_HALF) + HIST_BLKS, 256>>>(keys, W, b, idx4);
    segment_kernel<<<(M_SEG + 3) / 4, 128>>>(SV, out_applied);
    finalize_kernel<<<HIST_BLKS, 256>>>(idx4, (float4*)out_scores);
}